// round 16
// baseline (speedup 1.0000x reference)
#include <cuda_runtime.h>
#include <cuda_fp16.h>
#include <cstdint>
#include <math.h>

// Problem constants
#define N_GLOB 256
#define M_GLOB 1024
#define D_GLOB 512
#define H_GLOB 512

// Tiling: 256 pairs (32e x 8s) per CTA, H in 4 passes of 128, K slab 32
#define E_SUB    32
#define S_SUB    8
#define P_TILE   256
#define H_TILE   128
#define K_SLAB   32
#define N_PHASES 64           // 4 passes * 16 slabs
#define THREADS  512          // 16 warps: 4 m-warps x 4 n-warps (64x32 tiles)

// SMEM layout (byte offsets)
#define B1_OFF   0            // 512 f32
#define W2_OFF   2048         // 512 f32
#define PART_OFF 4096         // 256 f32
#define ES_OFF   5120         // [32][528] half (33792 B)  k-interleaved
#define SS_OFF   38912        // [8][528]  half (8448 B)   k-interleaved
#define SMEM_BYTES 47360

#define ES_STRIDE 528         // halfs per row

// W1 in fragment-major layout: [phase(64)][kt(2)][hpair(8)][lane(32)] uint4
__device__ static uint4 g_W1F[N_PHASES * 512];

__device__ __forceinline__ uint32_t h2_u32(__half2 h) {
    uint32_t u; __builtin_memcpy(&u, &h, 4); return u;
}
__device__ __forceinline__ __half2 u32_h2(uint32_t u) {
    __half2 h; __builtin_memcpy(&h, &u, 4); return h;
}
// |e - s| : HSUB2 on fma pipe + sign-clear LOP3 on alu pipe (bit-identical to habs2)
__device__ __forceinline__ uint32_t habs_sub(uint32_t e, uint32_t s) {
    return h2_u32(__hsub2(u32_h2(e), u32_h2(s))) & 0x7FFF7FFFu;
}

// ---- pre-kernel: W1 [D][H] f32 -> g_W1F fragment-major fp16 ----
// thread t -> one uint4: t = ((p*2 + kt)*8 + hp)*32 + lane
__global__ void convert_w1f_kernel(const float* __restrict__ W1) {
    const int t    = blockIdx.x * 256 + threadIdx.x;   // 0..32767
    const int lane = t & 31;
    const int hp   = (t >> 5) & 7;
    const int kt   = (t >> 8) & 1;
    const int p    = t >> 9;
    const int pass = p >> 4, slab = p & 15;
    const int kb   = slab * 32 + kt * 16 + (lane & 3) * 2;
    uint4 v;
    uint32_t w[4];
    #pragma unroll
    for (int j = 0; j < 2; ++j) {
        const int n = pass * 128 + hp * 16 + j * 8 + (lane >> 2);
        const __half2 b0 = __floats2half2_rn(W1[(size_t)kb * H_GLOB + n],
                                             W1[(size_t)(kb + 1) * H_GLOB + n]);
        const __half2 b1 = __floats2half2_rn(W1[(size_t)(kb + 8) * H_GLOB + n],
                                             W1[(size_t)(kb + 9) * H_GLOB + n]);
        w[j * 2 + 0] = h2_u32(b0);
        w[j * 2 + 1] = h2_u32(b1);
    }
    v.x = w[0]; v.y = w[1]; v.z = w[2]; v.w = w[3];
    g_W1F[t] = v;
}

__global__ void __launch_bounds__(THREADS, 1)
support_sp_kernel(const float* __restrict__ E,   // [N, D]
                  const float* __restrict__ S,   // [M, D]
                  const float* __restrict__ B1,  // [H]
                  const float* __restrict__ W2,  // [H]
                  const float* __restrict__ B2,  // [1]
                  float* __restrict__ out)       // [N, M]
{
    extern __shared__ char smem[];
    __half* smE  = (__half*)(smem + ES_OFF);
    __half* smS  = (__half*)(smem + SS_OFF);
    float*  smB1 = (float*)(smem + B1_OFF);
    float*  smW2 = (float*)(smem + W2_OFF);
    float*  smP  = (float*)(smem + PART_OFF);

    const int tid  = threadIdx.x;
    const int wid  = tid >> 5;
    const int lane = tid & 31;

    const int n0 = blockIdx.y * E_SUB;
    const int m0 = blockIdx.x * S_SUB;

    // ---- stage E/S as fp16, k-interleaved: block b of 8 half2, j -> (j<4 ? 2j : 2(j-4)+1)
    #pragma unroll
    for (int i = tid; i < 8192; i += THREADS) {       // E: 32 rows x 256 half2
        const int row = i >> 8, c2 = i & 255;
        const float2 v = *(const float2*)(E + (size_t)(n0 + row) * D_GLOB + c2 * 2);
        const int b = c2 >> 3, j = c2 & 7;
        const int nc2 = b * 8 + (j < 4 ? 2 * j : 2 * (j - 4) + 1);
        *(__half2*)(smE + row * ES_STRIDE + nc2 * 2) = __floats2half2_rn(v.x, v.y);
    }
    #pragma unroll
    for (int i = tid; i < 2048; i += THREADS) {       // S: 8 rows x 256 half2
        const int row = i >> 8, c2 = i & 255;
        const float2 v = *(const float2*)(S + (size_t)(m0 + row) * D_GLOB + c2 * 2);
        const int b = c2 >> 3, j = c2 & 7;
        const int nc2 = b * 8 + (j < 4 ? 2 * j : 2 * (j - 4) + 1);
        *(__half2*)(smS + row * ES_STRIDE + nc2 * 2) = __floats2half2_rn(v.x, v.y);
    }
    if (tid < 512) { smB1[tid] = B1[tid]; smW2[tid] = W2[tid]; }
    if (tid < P_TILE) smP[tid] = 0.f;
    __syncthreads();          // the ONLY barrier before the final reduction

    const int warp_m = wid & 3;       // 64-row quadrant (4 x 16-row tiles)
    const int warp_n = wid >> 2;      // 32-col H quadrant
    const int c = lane & 3;
    const int r = lane >> 2;

    float acc[4][4][4];
    float psum[8];
    #pragma unroll
    for (int i = 0; i < 8; ++i) psum[i] = 0.f;

    // free-running mainloop: B straight from global fragments, no cross-warp sync
    for (int p = 0; p < N_PHASES; ++p) {
        const int slab = p & 15;
        const int pass = p >> 4;

        if (slab == 0) {
            #pragma unroll
            for (int mt = 0; mt < 4; ++mt)
                #pragma unroll
                for (int nt = 0; nt < 4; ++nt)
                    #pragma unroll
                    for (int q = 0; q < 4; ++q) acc[mt][nt][q] = 0.f;
        }

        const uint4* __restrict__ gB = g_W1F + p * 512;
        #pragma unroll
        for (int kt = 0; kt < 2; ++kt) {
            const int bh = (slab * 2 + kt) * 16 + c * 4;   // half offset within row
            // ---- B fragments first (hide LDG latency behind A-build):
            //      2 LDG.128, each covers 2 nt ----
            const uint4 v0 = __ldg(gB + kt * 256 + (warp_n * 2 + 0) * 32 + lane);
            const uint4 v1 = __ldg(gB + kt * 256 + (warp_n * 2 + 1) * 32 + lane);
            // ---- A fragments: 9 LDS.64 + 16 HSUB2 (fma) + 16 LOP3 (alu) ----
            const uint2 us = *(const uint2*)(smS + r * ES_STRIDE + bh);
            uint32_t a[4][4];
            #pragma unroll
            for (int mt = 0; mt < 4; ++mt) {
                const int er = (warp_m * 4 + mt) * 2;
                const uint2 ue0 = *(const uint2*)(smE + er * ES_STRIDE + bh);
                const uint2 ue1 = *(const uint2*)(smE + (er + 1) * ES_STRIDE + bh);
                a[mt][0] = habs_sub(ue0.x, us.x);
                a[mt][1] = habs_sub(ue1.x, us.x);
                a[mt][2] = habs_sub(ue0.y, us.y);
                a[mt][3] = habs_sub(ue1.y, us.y);
            }
            #pragma unroll
            for (int mt = 0; mt < 4; ++mt) {
                asm volatile(
                    "mma.sync.aligned.m16n8k16.row.col.f32.f16.f16.f32 "
                    "{%0,%1,%2,%3}, {%4,%5,%6,%7}, {%8,%9}, {%0,%1,%2,%3};\n"
                    : "+f"(acc[mt][0][0]), "+f"(acc[mt][0][1]),
                      "+f"(acc[mt][0][2]), "+f"(acc[mt][0][3])
                    : "r"(a[mt][0]), "r"(a[mt][1]), "r"(a[mt][2]), "r"(a[mt][3]),
                      "r"(v0.x), "r"(v0.y));
                asm volatile(
                    "mma.sync.aligned.m16n8k16.row.col.f32.f16.f16.f32 "
                    "{%0,%1,%2,%3}, {%4,%5,%6,%7}, {%8,%9}, {%0,%1,%2,%3};\n"
                    : "+f"(acc[mt][1][0]), "+f"(acc[mt][1][1]),
                      "+f"(acc[mt][1][2]), "+f"(acc[mt][1][3])
                    : "r"(a[mt][0]), "r"(a[mt][1]), "r"(a[mt][2]), "r"(a[mt][3]),
                      "r"(v0.z), "r"(v0.w));
                asm volatile(
                    "mma.sync.aligned.m16n8k16.row.col.f32.f16.f16.f32 "
                    "{%0,%1,%2,%3}, {%4,%5,%6,%7}, {%8,%9}, {%0,%1,%2,%3};\n"
                    : "+f"(acc[mt][2][0]), "+f"(acc[mt][2][1]),
                      "+f"(acc[mt][2][2]), "+f"(acc[mt][2][3])
                    : "r"(a[mt][0]), "r"(a[mt][1]), "r"(a[mt][2]), "r"(a[mt][3]),
                      "r"(v1.x), "r"(v1.y));
                asm volatile(
                    "mma.sync.aligned.m16n8k16.row.col.f32.f16.f16.f32 "
                    "{%0,%1,%2,%3}, {%4,%5,%6,%7}, {%8,%9}, {%0,%1,%2,%3};\n"
                    : "+f"(acc[mt][3][0]), "+f"(acc[mt][3][1]),
                      "+f"(acc[mt][3][2]), "+f"(acc[mt][3][3])
                    : "r"(a[mt][0]), "r"(a[mt][1]), "r"(a[mt][2]), "r"(a[mt][3]),
                      "r"(v1.z), "r"(v1.w));
            }
        }

        if (slab == 15) {
            #pragma unroll
            for (int mt = 0; mt < 4; ++mt)
                #pragma unroll
                for (int nt = 0; nt < 4; ++nt) {
                    const int jg = pass * H_TILE + warp_n * 32 + nt * 8 + c * 2;
                    const float b1a = smB1[jg], b1b = smB1[jg + 1];
                    const float w2a = smW2[jg], w2b = smW2[jg + 1];
                    const float h0 = fmaxf(acc[mt][nt][0] + b1a, 0.f);
                    const float h1 = fmaxf(acc[mt][nt][1] + b1b, 0.f);
                    const float h2 = fmaxf(acc[mt][nt][2] + b1a, 0.f);
                    const float h3 = fmaxf(acc[mt][nt][3] + b1b, 0.f);
                    psum[mt * 2 + 0] += h0 * w2a + h1 * w2b;
                    psum[mt * 2 + 1] += h2 * w2a + h3 * w2b;
                }
        }
    }

    // ---- reduce across quad (k-cols of frag), then across 4 n-warps ----
    #pragma unroll
    for (int i = 0; i < 8; ++i) {
        psum[i] += __shfl_xor_sync(0xffffffffu, psum[i], 1);
        psum[i] += __shfl_xor_sync(0xffffffffu, psum[i], 2);
    }
    if (c == 0) {
        #pragma unroll
        for (int mt = 0; mt < 4; ++mt) {
            atomicAdd(&smP[warp_m * 64 + mt * 16 + r],     psum[mt * 2 + 0]);
            atomicAdd(&smP[warp_m * 64 + mt * 16 + r + 8], psum[mt * 2 + 1]);
        }
    }
    __syncthreads();

    if (tid < P_TILE) {
        const float logit = smP[tid] + B2[0];
        const int n = n0 + (tid >> 3);
        const int m = m0 + (tid & 7);
        out[(size_t)n * M_GLOB + m] = 1.f / (1.f + expf(-logit));
    }
}

extern "C" void kernel_launch(void* const* d_in, const int* in_sizes, int n_in,
                              void* d_out, int out_size)
{
    const float* E  = (const float*)d_in[0];
    const float* S  = (const float*)d_in[1];
    const float* W1 = (const float*)d_in[2];
    const float* B1 = (const float*)d_in[3];
    const float* W2 = (const float*)d_in[4];
    const float* B2 = (const float*)d_in[5];
    float* out = (float*)d_out;

    convert_w1f_kernel<<<128, 256>>>(W1);

    cudaFuncSetAttribute(support_sp_kernel,
                         cudaFuncAttributeMaxDynamicSharedMemorySize, SMEM_BYTES);
    dim3 grid(M_GLOB / S_SUB, N_GLOB / E_SUB);   // (128, 8) = 1024 CTAs
    support_sp_kernel<<<grid, THREADS, SMEM_BYTES>>>(E, S, B1, W2, B2, out);
}

// round 17
// speedup vs baseline: 1.0750x; 1.0750x over previous
#include <cuda_runtime.h>
#include <cuda_fp16.h>
#include <cstdint>
#include <math.h>

// Problem constants
#define N_GLOB 256
#define M_GLOB 1024
#define D_GLOB 512
#define H_GLOB 512

// Tiling: 256 pairs (32e x 8s) per CTA, H in 4 passes of 128, K slab 32
#define E_SUB    32
#define S_SUB    8
#define P_TILE   256
#define H_TILE   128
#define K_SLAB   32
#define N_PHASES 64           // 4 passes * 16 slabs
#define THREADS  512          // 16 warps: 8 m-warps x 2 n-warps

// SMEM layout (byte offsets)
#define B1_OFF   0            // 512 f32
#define W2_OFF   2048         // 512 f32
#define PART_OFF 4096         // 256 f32
#define ES_OFF   5120         // [32][528] half (33792 B)  k-interleaved
#define SS_OFF   38912        // [8][528]  half (8448 B)   k-interleaved
#define SMEM_BYTES 47360

#define ES_STRIDE 528         // halfs per row

// W1 in fragment-major layout: [phase(64)][kt(2)][hpair(8)][lane(32)] uint4
__device__ static uint4 g_W1F[N_PHASES * 512];

__device__ __forceinline__ uint32_t h2_u32(__half2 h) {
    uint32_t u; __builtin_memcpy(&u, &h, 4); return u;
}
__device__ __forceinline__ __half2 u32_h2(uint32_t u) {
    __half2 h; __builtin_memcpy(&h, &u, 4); return h;
}
// |e - s| : HSUB2 on fma pipe + sign-clear LOP3 on alu pipe (bit-identical to habs2)
__device__ __forceinline__ uint32_t habs_sub(uint32_t e, uint32_t s) {
    return h2_u32(__hsub2(u32_h2(e), u32_h2(s))) & 0x7FFF7FFFu;
}

// ---- pre-kernel: W1 [D][H] f32 -> g_W1F fragment-major fp16 ----
// thread t -> one uint4: t = ((p*2 + kt)*8 + hp)*32 + lane
__global__ void convert_w1f_kernel(const float* __restrict__ W1) {
    const int t    = blockIdx.x * 256 + threadIdx.x;   // 0..32767
    const int lane = t & 31;
    const int hp   = (t >> 5) & 7;
    const int kt   = (t >> 8) & 1;
    const int p    = t >> 9;
    const int pass = p >> 4, slab = p & 15;
    const int kb   = slab * 32 + kt * 16 + (lane & 3) * 2;
    uint4 v;
    uint32_t w[4];
    #pragma unroll
    for (int j = 0; j < 2; ++j) {
        const int n = pass * 128 + hp * 16 + j * 8 + (lane >> 2);
        const __half2 b0 = __floats2half2_rn(W1[(size_t)kb * H_GLOB + n],
                                             W1[(size_t)(kb + 1) * H_GLOB + n]);
        const __half2 b1 = __floats2half2_rn(W1[(size_t)(kb + 8) * H_GLOB + n],
                                             W1[(size_t)(kb + 9) * H_GLOB + n]);
        w[j * 2 + 0] = h2_u32(b0);
        w[j * 2 + 1] = h2_u32(b1);
    }
    v.x = w[0]; v.y = w[1]; v.z = w[2]; v.w = w[3];
    g_W1F[t] = v;
}

__global__ void __launch_bounds__(THREADS, 1)
support_sp_kernel(const float* __restrict__ E,   // [N, D]
                  const float* __restrict__ S,   // [M, D]
                  const float* __restrict__ B1,  // [H]
                  const float* __restrict__ W2,  // [H]
                  const float* __restrict__ B2,  // [1]
                  float* __restrict__ out)       // [N, M]
{
    extern __shared__ char smem[];
    __half* smE  = (__half*)(smem + ES_OFF);
    __half* smS  = (__half*)(smem + SS_OFF);
    float*  smB1 = (float*)(smem + B1_OFF);
    float*  smW2 = (float*)(smem + W2_OFF);
    float*  smP  = (float*)(smem + PART_OFF);

    const int tid  = threadIdx.x;
    const int wid  = tid >> 5;
    const int lane = tid & 31;

    const int n0 = blockIdx.y * E_SUB;
    const int m0 = blockIdx.x * S_SUB;

    // ---- stage E/S as fp16, k-interleaved: block b of 8 half2, j -> (j<4 ? 2j : 2(j-4)+1)
    #pragma unroll
    for (int i = tid; i < 8192; i += THREADS) {       // E: 32 rows x 256 half2
        const int row = i >> 8, c2 = i & 255;
        const float2 v = *(const float2*)(E + (size_t)(n0 + row) * D_GLOB + c2 * 2);
        const int b = c2 >> 3, j = c2 & 7;
        const int nc2 = b * 8 + (j < 4 ? 2 * j : 2 * (j - 4) + 1);
        *(__half2*)(smE + row * ES_STRIDE + nc2 * 2) = __floats2half2_rn(v.x, v.y);
    }
    #pragma unroll
    for (int i = tid; i < 2048; i += THREADS) {       // S: 8 rows x 256 half2
        const int row = i >> 8, c2 = i & 255;
        const float2 v = *(const float2*)(S + (size_t)(m0 + row) * D_GLOB + c2 * 2);
        const int b = c2 >> 3, j = c2 & 7;
        const int nc2 = b * 8 + (j < 4 ? 2 * j : 2 * (j - 4) + 1);
        *(__half2*)(smS + row * ES_STRIDE + nc2 * 2) = __floats2half2_rn(v.x, v.y);
    }
    if (tid < 512) { smB1[tid] = B1[tid]; smW2[tid] = W2[tid]; }
    if (tid < P_TILE) smP[tid] = 0.f;
    __syncthreads();          // the ONLY barrier before the final reduction

    const int warp_m = wid & 7;       // 32-row block (2 x 16-row tiles)
    const int warp_n = wid >> 3;      // 64-col H half
    const int c = lane & 3;
    const int r = lane >> 2;

    float acc[2][8][4];
    float psum[4] = {0.f, 0.f, 0.f, 0.f};

    // free-running mainloop: B straight from global fragments, no cross-warp sync
    for (int p = 0; p < N_PHASES; ++p) {
        const int slab = p & 15;
        const int pass = p >> 4;

        if (slab == 0) {
            #pragma unroll
            for (int mt = 0; mt < 2; ++mt)
                #pragma unroll
                for (int nt = 0; nt < 8; ++nt)
                    #pragma unroll
                    for (int q = 0; q < 4; ++q) acc[mt][nt][q] = 0.f;
        }

        const uint4* __restrict__ gB = g_W1F + p * 512;
        #pragma unroll
        for (int kt = 0; kt < 2; ++kt) {
            const int bh = (slab * 2 + kt) * 16 + c * 4;   // half offset within row
            // ---- A fragments: 5 LDS.64 + 16 HSUB2 (fma) + 16 LOP3 (alu) ----
            const uint2 us = *(const uint2*)(smS + r * ES_STRIDE + bh);
            uint32_t a[2][4];
            #pragma unroll
            for (int mt = 0; mt < 2; ++mt) {
                const int er = (warp_m * 2 + mt) * 2;
                const uint2 ue0 = *(const uint2*)(smE + er * ES_STRIDE + bh);
                const uint2 ue1 = *(const uint2*)(smE + (er + 1) * ES_STRIDE + bh);
                a[mt][0] = habs_sub(ue0.x, us.x);
                a[mt][1] = habs_sub(ue1.x, us.x);
                a[mt][2] = habs_sub(ue0.y, us.y);
                a[mt][3] = habs_sub(ue1.y, us.y);
            }
            // ---- B fragments: 4 LDG.128 (L1/L2-cached), each covers 2 nt ----
            #pragma unroll
            for (int hl = 0; hl < 4; ++hl) {
                const uint4 v = __ldg(gB + kt * 256 + (warp_n * 4 + hl) * 32 + lane);
                const int nt0 = hl * 2, nt1 = hl * 2 + 1;
                #pragma unroll
                for (int mt = 0; mt < 2; ++mt) {
                    asm volatile(
                        "mma.sync.aligned.m16n8k16.row.col.f32.f16.f16.f32 "
                        "{%0,%1,%2,%3}, {%4,%5,%6,%7}, {%8,%9}, {%0,%1,%2,%3};\n"
                        : "+f"(acc[mt][nt0][0]), "+f"(acc[mt][nt0][1]),
                          "+f"(acc[mt][nt0][2]), "+f"(acc[mt][nt0][3])
                        : "r"(a[mt][0]), "r"(a[mt][1]), "r"(a[mt][2]), "r"(a[mt][3]),
                          "r"(v.x), "r"(v.y));
                }
                #pragma unroll
                for (int mt = 0; mt < 2; ++mt) {
                    asm volatile(
                        "mma.sync.aligned.m16n8k16.row.col.f32.f16.f16.f32 "
                        "{%0,%1,%2,%3}, {%4,%5,%6,%7}, {%8,%9}, {%0,%1,%2,%3};\n"
                        : "+f"(acc[mt][nt1][0]), "+f"(acc[mt][nt1][1]),
                          "+f"(acc[mt][nt1][2]), "+f"(acc[mt][nt1][3])
                        : "r"(a[mt][0]), "r"(a[mt][1]), "r"(a[mt][2]), "r"(a[mt][3]),
                          "r"(v.z), "r"(v.w));
                }
            }
        }

        if (slab == 15) {
            #pragma unroll
            for (int mt = 0; mt < 2; ++mt)
                #pragma unroll
                for (int nt = 0; nt < 8; ++nt) {
                    const int jg = pass * H_TILE + warp_n * 64 + nt * 8 + c * 2;
                    const float b1a = smB1[jg], b1b = smB1[jg + 1];
                    const float w2a = smW2[jg], w2b = smW2[jg + 1];
                    const float h0 = fmaxf(acc[mt][nt][0] + b1a, 0.f);
                    const float h1 = fmaxf(acc[mt][nt][1] + b1b, 0.f);
                    const float h2 = fmaxf(acc[mt][nt][2] + b1a, 0.f);
                    const float h3 = fmaxf(acc[mt][nt][3] + b1b, 0.f);
                    psum[mt * 2 + 0] += h0 * w2a + h1 * w2b;
                    psum[mt * 2 + 1] += h2 * w2a + h3 * w2b;
                }
        }
    }

    // ---- reduce across quad (k-cols of frag), then across 2 n-warps ----
    #pragma unroll
    for (int i = 0; i < 4; ++i) {
        psum[i] += __shfl_xor_sync(0xffffffffu, psum[i], 1);
        psum[i] += __shfl_xor_sync(0xffffffffu, psum[i], 2);
    }
    if (c == 0) {
        #pragma unroll
        for (int mt = 0; mt < 2; ++mt) {
            atomicAdd(&smP[warp_m * 32 + mt * 16 + r],     psum[mt * 2 + 0]);
            atomicAdd(&smP[warp_m * 32 + mt * 16 + r + 8], psum[mt * 2 + 1]);
        }
    }
    __syncthreads();

    if (tid < P_TILE) {
        const float logit = smP[tid] + B2[0];
        const int n = n0 + (tid >> 3);
        const int m = m0 + (tid & 7);
        out[(size_t)n * M_GLOB + m] = 1.f / (1.f + expf(-logit));
    }
}

extern "C" void kernel_launch(void* const* d_in, const int* in_sizes, int n_in,
                              void* d_out, int out_size)
{
    const float* E  = (const float*)d_in[0];
    const float* S  = (const float*)d_in[1];
    const float* W1 = (const float*)d_in[2];
    const float* B1 = (const float*)d_in[3];
    const float* W2 = (const float*)d_in[4];
    const float* B2 = (const float*)d_in[5];
    float* out = (float*)d_out;

    convert_w1f_kernel<<<128, 256>>>(W1);

    cudaFuncSetAttribute(support_sp_kernel,
                         cudaFuncAttributeMaxDynamicSharedMemorySize, SMEM_BYTES);
    dim3 grid(M_GLOB / S_SUB, N_GLOB / E_SUB);   // (128, 8) = 1024 CTAs
    support_sp_kernel<<<grid, THREADS, SMEM_BYTES>>>(E, S, B1, W2, B2, out);
}